// round 13
// baseline (speedup 1.0000x reference)
#include <cuda_runtime.h>
#include <cstdint>

#define B_   128
#define T_   512
#define DIM_ 256
#define E_   512
#define H_   512

// ---------------- device scratch ----------------
__device__ float g_xtf[(size_t)B_ * T_ * DIM_];       // x, tf32 bits
__device__ float g_Wetf[E_ * DIM_];                   // We, tf32 bits
__device__ float g_xe[(size_t)B_ * T_ * E_];          // xe, tf32 bits (GEMM1 out)
__device__ float g_gates[(size_t)T_ * B_ * 2048];     // [t][b][mcol] fp32
__device__ float g_Wall[2048 * 512];                  // packed gate weights, tf32 bits
__device__ float g_ball[2048];
__device__ float g_hP[2 * 16 * 64 * 32 * 2];          // [buf][bn][ks][lane][2] (tf32 bits)
__device__ unsigned g_cnt2[4];
__device__ volatile unsigned g_gen2[4];

// ---------------- helpers ----------------
__device__ __forceinline__ unsigned tf32_(float f) {
    unsigned u;
    asm("cvt.rna.tf32.f32 %0, %1;" : "=r"(u) : "f"(f));
    return u;
}
__device__ __forceinline__ float tf32f_(float f) {
    return __uint_as_float(tf32_(f));
}

__device__ __forceinline__ void mma_tf32(float* d, const unsigned* a, unsigned b0, unsigned b1) {
    asm volatile(
        "mma.sync.aligned.m16n8k8.row.col.f32.tf32.tf32.f32 "
        "{%0,%1,%2,%3}, {%4,%5,%6,%7}, {%8,%9}, {%0,%1,%2,%3};"
        : "+f"(d[0]), "+f"(d[1]), "+f"(d[2]), "+f"(d[3])
        : "r"(a[0]), "r"(a[1]), "r"(a[2]), "r"(a[3]), "r"(b0), "r"(b1));
}

__device__ __forceinline__ float sigmoidf_(float x) {
    return 1.0f / (1.0f + __expf(-x));
}

__device__ __forceinline__ void cp_async16(unsigned* dst_smem, const void* src) {
    unsigned d = (unsigned)__cvta_generic_to_shared(dst_smem);
    asm volatile("cp.async.ca.shared.global [%0], [%1], 16;" :: "r"(d), "l"(src));
}

// ---------------- fp32 -> tf32 bit conversion pass ----------------
__global__ void __launch_bounds__(256)
conv_tf32(const float4* __restrict__ src, float4* __restrict__ dst, int n4)
{
    const int i = blockIdx.x * 256 + threadIdx.x;
    if (i < n4) {
        float4 v = src[i];
        dst[i] = make_float4(tf32f_(v.x), tf32f_(v.y), tf32f_(v.z), tf32f_(v.w));
    }
}

// ---------------- pack gate weights (tf32 bits): row mcol = hcol*4+gate -----
__global__ void __launch_bounds__(256)
pack_w(const float* __restrict__ Wi, const float* __restrict__ Wf,
       const float* __restrict__ Wg, const float* __restrict__ Wo,
       const float* __restrict__ bi, const float* __restrict__ bf,
       const float* __restrict__ bg, const float* __restrict__ bo)
{
    const int idx = blockIdx.x * 256 + threadIdx.x;   // 2048*128 float4s
    const int n = idx >> 7, kq = idx & 127;
    const int gate = n & 3, hc = n >> 2;
    const float* W = (gate == 0) ? Wi : (gate == 1) ? Wf : (gate == 2) ? Wg : Wo;
    float4 v = *(const float4*)(W + (size_t)hc * 512 + kq * 4);
    *(float4*)(g_Wall + (size_t)n * 512 + kq * 4) =
        make_float4(tf32f_(v.x), tf32f_(v.y), tf32f_(v.z), tf32f_(v.w));
    if (kq == 0) {
        const float* bb = (gate == 0) ? bi : (gate == 1) ? bf : (gate == 2) ? bg : bo;
        g_ball[n] = bb[hc];
    }
}

// ---------------- cp.async pipelined tf32 GEMM: C = A @ W^T + bias ----------
// 256 threads, 128x128 block tile, BK=32, 2-stage cp.async pipeline.
// Inputs are pre-converted tf32 bits.
// MODE 0: A=g_xtf, W=g_Wetf, out -> g_xe (tf32 bits)   [KDIM=256, N=512]
// MODE 1: A=g_xe,  W=g_Wall, out -> g_gates fp32        [KDIM=512, N=2048]
template <int KDIM, int MODE>
__global__ void __launch_bounds__(256)
gemm_pipe(const unsigned* __restrict__ A_, const unsigned* __restrict__ W_,
          const float* __restrict__ bias_)
{
    extern __shared__ unsigned smemu[];
    unsigned* As = smemu;                 // [2][128*36]
    unsigned* Ws = smemu + 2 * 4608;      // [2][128*36]

    const unsigned* A = (MODE == 0) ? A_ : (const unsigned*)g_xe;
    const unsigned* W = (MODE == 0) ? W_ : (const unsigned*)g_Wall;
    const float* bias = (MODE == 0) ? bias_ : g_ball;

    const int tid = threadIdx.x, lane = tid & 31, warp = tid >> 5;
    const int wm = warp >> 1, wn = warp & 1;
    const int m0 = blockIdx.y * 128, n0 = blockIdx.x * 128;
    const int g = lane >> 2, t = lane & 3;

    // staging: 4 A-float4 + 4 W-float4 per thread per stage
    const int sr = tid >> 3;          // not used directly; see loop
    (void)sr;

    auto stage = [&](int st, int kk) {
#pragma unroll
        for (int p = 0; p < 4; p++) {
            const int idx = tid + p * 256;
            const int r = idx >> 3, kq = idx & 7;
            cp_async16(&As[st * 4608 + r * 36 + kq * 4], A + (size_t)(m0 + r) * KDIM + kk + kq * 4);
            cp_async16(&Ws[st * 4608 + r * 36 + kq * 4], W + (size_t)(n0 + r) * KDIM + kk + kq * 4);
        }
        asm volatile("cp.async.commit_group;");
    };

    stage(0, 0);

    float acc[2][8][4];
#pragma unroll
    for (int mt = 0; mt < 2; mt++)
#pragma unroll
        for (int nt = 0; nt < 8; nt++)
#pragma unroll
            for (int r = 0; r < 4; r++) acc[mt][nt][r] = 0.0f;

    const int NITER = KDIM / 32;
    for (int it = 0; it < NITER; it++) {
        const int st = it & 1;
        if (it + 1 < NITER) {
            stage(st ^ 1, (it + 1) * 32);
            asm volatile("cp.async.wait_group 1;");
        } else {
            asm volatile("cp.async.wait_group 0;");
        }
        __syncthreads();

        const unsigned* Ab = As + st * 4608;
        const unsigned* Wb = Ws + st * 4608;
#pragma unroll
        for (int s = 0; s < 4; s++) {
            unsigned af[2][4], bf[8][2];
#pragma unroll
            for (int mt = 0; mt < 2; mt++) {
                const int r = (wm * 32 + mt * 16 + g) * 36 + s * 8 + t;
                af[mt][0] = Ab[r];
                af[mt][1] = Ab[r + 288];
                af[mt][2] = Ab[r + 4];
                af[mt][3] = Ab[r + 292];
            }
#pragma unroll
            for (int nt = 0; nt < 8; nt++) {
                const int r = (wn * 64 + nt * 8 + g) * 36 + s * 8 + t;
                bf[nt][0] = Wb[r];
                bf[nt][1] = Wb[r + 4];
            }
#pragma unroll
            for (int mt = 0; mt < 2; mt++)
#pragma unroll
                for (int nt = 0; nt < 8; nt++)
                    mma_tf32(acc[mt][nt], af[mt], bf[nt][0], bf[nt][1]);
        }
        __syncthreads();
    }

    // ---- epilogue ----
#pragma unroll
    for (int mt = 0; mt < 2; mt++) {
        const int row0 = m0 + wm * 32 + mt * 16 + g;
#pragma unroll
        for (int nt = 0; nt < 8; nt++) {
            const int col = n0 + wn * 64 + nt * 8 + t * 2;
            const float2 bv = *(const float2*)(bias + col);
            const float a0 = acc[mt][nt][0] + bv.x, a1 = acc[mt][nt][1] + bv.y;
            const float a2 = acc[mt][nt][2] + bv.x, a3 = acc[mt][nt][3] + bv.y;
            if (MODE == 0) {
                // emit tf32 bits (consumed by GEMM2) — same quantization point as before
                *(float2*)(g_xe + (size_t)row0 * E_ + col)       = make_float2(tf32f_(a0), tf32f_(a1));
                *(float2*)(g_xe + (size_t)(row0 + 8) * E_ + col) = make_float2(tf32f_(a2), tf32f_(a3));
            } else {
                const int b0v = row0 >> 9, t0v = row0 & 511;
                const int b1v = (row0 + 8) >> 9, t1v = (row0 + 8) & 511;
                *(float2*)(g_gates + ((size_t)t0v * B_ + b0v) * 2048 + col) = make_float2(a0, a1);
                *(float2*)(g_gates + ((size_t)t1v * B_ + b1v) * 2048 + col) = make_float2(a2, a3);
            }
        }
    }
}

// ---------------- group barrier (32 blocks per batch-group) ----------------
__device__ __forceinline__ void group_barrier32(int ng) {
    __threadfence();
    __syncthreads();
    if (threadIdx.x == 0) {
        unsigned g = g_gen2[ng];
        unsigned old = atomicAdd(&g_cnt2[ng], 1u);
        if (old == 31u) {
            g_cnt2[ng] = 0u;
            __threadfence();
            g_gen2[ng] = g + 1u;
        } else {
            while (g_gen2[ng] == g) __nanosleep(20);
        }
        __threadfence();
    }
    __syncthreads();
}

// ---------------- persistent tf32-MMA recurrence, R in registers ------------
// (unchanged from R10 — known good)
__global__ void __launch_bounds__(512, 1)
lstm_rec(const float* __restrict__ h0, const float* __restrict__ c0,
         const float* __restrict__ Ri, const float* __restrict__ Rf,
         const float* __restrict__ Rg, const float* __restrict__ Ro,
         float* __restrict__ out)
{
    extern __shared__ float smem[];
    float* hS   = smem;                    // 16384 floats = 64 KB (h tile, hP layout)
    float* pbuf = smem + 16384;            // [8 wk][64 row][33] = 16896 floats

    const int tid  = threadIdx.x;
    const int lane = tid & 31;
    const int w    = tid >> 5;
    const int wm   = w >> 3;               // m32 half (0..1)
    const int wk   = w & 7;                // K eighth (0..7)
    const int gid  = lane >> 2;
    const int tig  = lane & 3;

    const int mg = blockIdx.x & 31;
    const int ng = blockIdx.x >> 5;
    const int hcol0 = mg * 16;
    const int batch0 = ng * 32;
    const int M0 = mg * 64;

    // ---- one-time: stage R tile (tf32) into smem scratch, coalesced ----
    {
        const float* Rp[4] = { Ri, Rf, Rg, Ro };
#pragma unroll 1
        for (int i = 0; i < 16; i++) {
            const int f4 = tid + i * 512;          // 8192 float4s
            const int row = f4 >> 7, c4 = f4 & 127;
            const float* src = Rp[row & 3] + (size_t)(hcol0 + (row >> 2)) * H_ + c4 * 4;
            float4 v = *(const float4*)src;
            *(float4*)(smem + row * 512 + c4 * 4) =
                make_float4(tf32f_(v.x), tf32f_(v.y), tf32f_(v.z), tf32f_(v.w));
        }
    }
    __syncthreads();

    // ---- one-time: gather A fragments into registers ----
    uint4 ar[16];   // [mt 2][ks8 8]
#pragma unroll
    for (int mt = 0; mt < 2; mt++)
#pragma unroll
        for (int k8 = 0; k8 < 8; k8++) {
            const int r0 = wm * 32 + mt * 16 + gid;
            const int kk = wk * 64 + k8 * 8 + tig;
            uint4 v;
            v.x = __float_as_uint(smem[r0 * 512 + kk]);
            v.y = __float_as_uint(smem[(r0 + 8) * 512 + kk]);
            v.z = __float_as_uint(smem[r0 * 512 + kk + 4]);
            v.w = __float_as_uint(smem[(r0 + 8) * 512 + kk + 4]);
            ar[mt * 8 + k8] = v;
        }
    __syncthreads();   // scratch dead; hS/pbuf reuse begins

    // ---- init c state + publish h[0]; 1 cell per thread ----
    const int bl = tid >> 4;               // local batch (0..31)
    const int hl = tid & 15;               // local hcol (0..15)
    const int jj = hcol0 + hl;
    const int bb = batch0 + bl;
    float creg;
    {
        creg = c0[(size_t)bb * H_ + jj];
        const float hv = h0[(size_t)bb * H_ + jj];
        const size_t hidx = (((size_t)(bb >> 3) * 64 + (jj >> 3)) * 32 + ((bb & 7) * 4 + (jj & 3))) * 2 + ((jj >> 2) & 1);
        g_hP[hidx] = __uint_as_float(tf32_(hv));
    }

    // ---- gate prefetch t=0 ----
    const float* gpbase = g_gates + ((size_t)bb) * 2048 + M0 + hl * 4;
    float4 u = __ldg((const float4*)gpbase);

    const float2* hS2 = (const float2*)hS;
    float* pb = pbuf + wk * 2112;
    const size_t BTH = (size_t)B_ * T_ * H_;
    const int ksbase = wk * 8;

    for (int t = 0; t < T_; t++) {
        group_barrier32(ng);               // h[t] published by all producers

        // ---- stage h tile (64 KB = 4096 uint4) into smem ----
        {
            const float4* src4 = (const float4*)g_hP + (size_t)(t & 1) * 16384 + ng * 4096;
            float4* dst4 = (float4*)hS;
#pragma unroll
            for (int i = 0; i < 8; i++)
                dst4[tid + i * 512] = __ldcg(src4 + tid + i * 512);
        }
        __syncthreads();

        // ---- MMA: A from regs, B from hS; mt=2 x nt=4 over K-eighth ----
        float acc[2][4][4];
#pragma unroll
        for (int i = 0; i < 2; i++)
#pragma unroll
            for (int j = 0; j < 4; j++)
#pragma unroll
                for (int r = 0; r < 4; r++) acc[i][j][r] = 0.0f;

#pragma unroll
        for (int k8 = 0; k8 < 8; k8++) {
            const int ks = ksbase + k8;
#pragma unroll
            for (int j = 0; j < 4; j++) {
                float2 b = hS2[(j * 64 + ks) * 32 + lane];
                const unsigned bx = __float_as_uint(b.x), by = __float_as_uint(b.y);
                mma_tf32(acc[0][j], (const unsigned*)&ar[k8],     bx, by);
                mma_tf32(acc[1][j], (const unsigned*)&ar[8 + k8], bx, by);
            }
        }

        // ---- store K-partials to pbuf[wk] ----
#pragma unroll
        for (int i = 0; i < 2; i++) {
            const int r = wm * 32 + i * 16 + gid;
#pragma unroll
            for (int j = 0; j < 4; j++) {
                const int c = j * 8 + tig * 2;
                pb[r * 33 + c]           = acc[i][j][0];
                pb[r * 33 + c + 1]       = acc[i][j][1];
                pb[(r + 8) * 33 + c]     = acc[i][j][2];
                pb[(r + 8) * 33 + c + 1] = acc[i][j][3];
            }
        }
        __syncthreads();

        // ---- LSTM cell update: sum 8 K-partials + gate regs, publish h ----
        float p[4];
#pragma unroll
        for (int gte = 0; gte < 4; gte++) {
            const int ro = (hl * 4 + gte) * 33 + bl;
            float s = pbuf[ro];
#pragma unroll
            for (int sl = 1; sl < 8; sl++) s += pbuf[sl * 2112 + ro];
            p[gte] = s;
        }
        const float ig = sigmoidf_(p[0] + u.x);
        const float fg = sigmoidf_(p[1] + u.y);
        const float gg = tanhf(p[2] + u.z);
        const float og = sigmoidf_(p[3] + u.w);
        const float cn2 = gg * ig + fg * creg;
        creg = cn2;
        const float hn = og * tanhf(cn2);

        if (t + 1 < T_) {
            const size_t hidx = ((size_t)((t + 1) & 1) * 16 * 64 * 32
                                 + ((size_t)(bb >> 3) * 64 + (jj >> 3)) * 32
                                 + ((bb & 7) * 4 + (jj & 3))) * 2 + ((jj >> 2) & 1);
            g_hP[hidx] = __uint_as_float(tf32_(hn));
        }

        // ---- shadow work: out stores + next gate prefetch ----
        out[(size_t)bb * (T_ * H_) + (size_t)t * H_ + jj] = hn;
        if (t == T_ - 1) {
            out[BTH + (size_t)bb * H_ + jj] = hn;
            out[BTH + (size_t)(B_ * H_) + (size_t)bb * H_ + jj] = cn2;
        }
        if (t + 1 < T_) {
            u = __ldg((const float4*)(gpbase + (size_t)(t + 1) * (B_ * 2048)));
        }
    }
}

// ---------------- launch ----------------
extern "C" void kernel_launch(void* const* d_in, const int* in_sizes, int n_in,
                              void* d_out, int out_size)
{
    (void)in_sizes; (void)n_in; (void)out_size;
    const float* x  = (const float*)d_in[0];
    const float* h0 = (const float*)d_in[1];
    const float* c0 = (const float*)d_in[2];
    const float* We = (const float*)d_in[3];
    const float* be = (const float*)d_in[4];
    const float* Wf = (const float*)d_in[5];
    const float* bf = (const float*)d_in[6];
    const float* Wi = (const float*)d_in[7];
    const float* bi = (const float*)d_in[8];
    const float* Wg = (const float*)d_in[9];
    const float* bg = (const float*)d_in[10];
    const float* Wo = (const float*)d_in[11];
    const float* bo = (const float*)d_in[12];
    const float* Rf = (const float*)d_in[13];
    const float* Ri = (const float*)d_in[14];
    const float* Rg = (const float*)d_in[15];
    const float* Ro = (const float*)d_in[16];
    float* out = (float*)d_out;

    static bool attr_set = false;
    if (!attr_set) {
        cudaFuncSetAttribute(lstm_rec,
                             cudaFuncAttributeMaxDynamicSharedMemorySize, 135168);
        cudaFuncSetAttribute(gemm_pipe<DIM_, 0>,
                             cudaFuncAttributeMaxDynamicSharedMemorySize, 73728);
        cudaFuncSetAttribute(gemm_pipe<E_, 1>,
                             cudaFuncAttributeMaxDynamicSharedMemorySize, 73728);
        attr_set = true;
    }

    float* d_xtf;  cudaGetSymbolAddress((void**)&d_xtf,  g_xtf);
    float* d_Wetf; cudaGetSymbolAddress((void**)&d_Wetf, g_Wetf);

    // pre-convert x and We to tf32 bits
    conv_tf32<<<(B_ * T_ * DIM_ / 4 + 255) / 256, 256>>>((const float4*)x, (float4*)d_xtf, B_ * T_ * DIM_ / 4);
    conv_tf32<<<(E_ * DIM_ / 4 + 255) / 256, 256>>>((const float4*)We, (float4*)d_Wetf, E_ * DIM_ / 4);

    // pack gate weights (tf32 bits, i,f,g,o interleaved by mcol)
    pack_w<<<1024, 256>>>(Wi, Wf, Wg, Wo, bi, bf, bg, bo);

    // xe = x @ We^T + be  (cp.async pipelined tf32 MMA)
    gemm_pipe<DIM_, 0><<<dim3(E_ / 128, (B_ * T_) / 128), 256, 73728>>>(
        (const unsigned*)d_xtf, (const unsigned*)d_Wetf, be);

    // gates = xe @ Wall^T + ball  (N=2048)
    gemm_pipe<E_, 1><<<dim3(2048 / 128, (B_ * T_) / 128), 256, 73728>>>(
        nullptr, nullptr, nullptr);

    // persistent tf32 recurrence (R-in-registers, counting-barrier sync)
    const int dynsmem = (16384 + 16896) * 4;   // hS 64K + pbuf 67.6K = 133120 B
    lstm_rec<<<128, 512, dynsmem>>>(h0, c0, Ri, Rf, Rg, Ro, out);
}